// round 2
// baseline (speedup 1.0000x reference)
#include <cuda_runtime.h>

#define BB 8192
#define LL 200
#define QQ 128
#define HH 128

// qw scratch: qw[b][h] = sum_q query[b][q] * W[q][h]   (4 MB, static device array)
__device__ float g_qw[BB * HH];
// 1 if hist_behavior_length buffer is int64, 0 if int32 (detected at runtime)
__device__ int g_len_is64;

// ---------------------------------------------------------------------------
// Kernel 0: detect length dtype. int64 values in [0,200) -> all odd dwords 0.
// ---------------------------------------------------------------------------
__global__ void detect_len_dtype_kernel(const int* __restrict__ len32)
{
    if (threadIdx.x == 0) {
        int nz = 0;
#pragma unroll
        for (int i = 1; i < 256; i += 2) nz += (len32[i] != 0);
        g_len_is64 = (nz == 0) ? 1 : 0;
    }
}

// ---------------------------------------------------------------------------
// Kernel 1: qw = query @ W   (small register-tiled GEMM)
// grid = 128 CTAs, 256 threads, each CTA computes 64 rows of qw.
// ---------------------------------------------------------------------------
__global__ __launch_bounds__(256, 2) void qw_gemm_kernel(
    const float* __restrict__ query, const float* __restrict__ W)
{
    extern __shared__ float smem1[];
    float* sW = smem1;                 // [128][128]
    float* sQ = smem1 + QQ * HH;       // [64][132] padded

    const int tid = threadIdx.x;
    const int b0  = blockIdx.x * 64;

    const float4* W4 = (const float4*)W;
    float4* sW4 = (float4*)sW;
#pragma unroll
    for (int i = 0; i < 16; ++i)
        sW4[tid + i * 256] = W4[tid + i * 256];

    const float4* Q4 = (const float4*)(query + (size_t)b0 * QQ);
#pragma unroll
    for (int i = 0; i < 8; ++i) {
        int idx = tid + i * 256;           // 0..2047
        int r = idx >> 5;
        int c = (idx & 31) << 2;
        float4 v = Q4[idx];
        *(float4*)&sQ[r * 132 + c] = v;
    }
    __syncthreads();

    const int j  = tid & 15;
    const int i  = tid >> 4;
    const int r0 = i * 4;
    const int h0 = j * 8;

    float acc[4][8];
#pragma unroll
    for (int a = 0; a < 4; ++a)
#pragma unroll
        for (int c = 0; c < 8; ++c) acc[a][c] = 0.f;

#pragma unroll 4
    for (int q = 0; q < QQ; ++q) {
        float4 w0 = *(const float4*)&sW[q * HH + h0];
        float4 w1 = *(const float4*)&sW[q * HH + h0 + 4];
        float wv[8] = {w0.x, w0.y, w0.z, w0.w, w1.x, w1.y, w1.z, w1.w};
        float qv[4];
#pragma unroll
        for (int a = 0; a < 4; ++a) qv[a] = sQ[(r0 + a) * 132 + q];
#pragma unroll
        for (int a = 0; a < 4; ++a)
#pragma unroll
            for (int c = 0; c < 8; ++c)
                acc[a][c] = fmaf(qv[a], wv[c], acc[a][c]);
    }

#pragma unroll
    for (int a = 0; a < 4; ++a) {
        float4 o0 = {acc[a][0], acc[a][1], acc[a][2], acc[a][3]};
        float4 o1 = {acc[a][4], acc[a][5], acc[a][6], acc[a][7]};
        float* dst = g_qw + (size_t)(b0 + r0 + a) * HH + h0;
        *(float4*)dst       = o0;
        *(float4*)(dst + 4) = o1;
    }
}

// ---------------------------------------------------------------------------
// Kernel 2: fused attention-pooling per batch row.
// One CTA per b. hist row (102.4KB) streamed HBM->SMEM once; logits computed
// en-route; softmax in SMEM; weighted sum reads SMEM only.
// ---------------------------------------------------------------------------
__global__ __launch_bounds__(256, 2) void attn_pool_kernel(
    const float* __restrict__ hist, const void* __restrict__ hlen,
    float* __restrict__ out)
{
    extern __shared__ float smem[];
    float*  s_hist   = smem;
    float*  s_logits = smem + LL * HH;         // 25600
    float*  s_red    = s_logits + 256;         // 25856
    float4* s_part   = (float4*)(s_red + 16);  // 25872 (16B aligned)

    const int b    = blockIdx.x;
    const int tid  = threadIdx.x;
    const int warp = tid >> 5;
    const int lane = tid & 31;

    const float4 qwv = ((const float4*)(g_qw + (size_t)b * HH))[lane];

    const float4* h4   = (const float4*)(hist + (size_t)b * LL * HH);
    float4*       s_h4 = (float4*)s_hist;

    // ---- pass 1: stream hist, stage to SMEM, compute logits ----
#pragma unroll
    for (int it = 0; it < 25; ++it) {
        const int l = warp + it * 8;
        float4 v = h4[l * 32 + lane];
        s_h4[l * 32 + lane] = v;
        float p = v.x * qwv.x + v.y * qwv.y + v.z * qwv.z + v.w * qwv.w;
        p += __shfl_xor_sync(0xffffffffu, p, 16);
        p += __shfl_xor_sync(0xffffffffu, p, 8);
        p += __shfl_xor_sync(0xffffffffu, p, 4);
        p += __shfl_xor_sync(0xffffffffu, p, 2);
        p += __shfl_xor_sync(0xffffffffu, p, 1);
        if (lane == 0) s_logits[l] = p;
    }
    __syncthreads();

    // ---- mask + softmax over 200 positions ----
    long long Lb;
    if (g_len_is64) Lb = ((const long long*)hlen)[b];
    else            Lb = (long long)((const int*)hlen)[b];

    float lg = -1e30f;
    if (tid < LL) {
        lg = s_logits[tid];
        if ((long long)tid < Lb) lg = 1e-9f;   // faithful to reference mask
    }

    float m = lg;
    m = fmaxf(m, __shfl_xor_sync(0xffffffffu, m, 16));
    m = fmaxf(m, __shfl_xor_sync(0xffffffffu, m, 8));
    m = fmaxf(m, __shfl_xor_sync(0xffffffffu, m, 4));
    m = fmaxf(m, __shfl_xor_sync(0xffffffffu, m, 2));
    m = fmaxf(m, __shfl_xor_sync(0xffffffffu, m, 1));
    if (lane == 0) s_red[warp] = m;
    __syncthreads();
    if (tid == 0) {
        float mm = s_red[0];
#pragma unroll
        for (int k = 1; k < 8; ++k) mm = fmaxf(mm, s_red[k]);
        s_red[8] = mm;
    }
    __syncthreads();
    const float mx = s_red[8];

    float e = (tid < LL) ? __expf(lg - mx) : 0.f;
    float s = e;
    s += __shfl_xor_sync(0xffffffffu, s, 16);
    s += __shfl_xor_sync(0xffffffffu, s, 8);
    s += __shfl_xor_sync(0xffffffffu, s, 4);
    s += __shfl_xor_sync(0xffffffffu, s, 2);
    s += __shfl_xor_sync(0xffffffffu, s, 1);
    __syncthreads();
    if (lane == 0) s_red[warp] = s;
    __syncthreads();
    if (tid == 0) {
        float tot = s_red[0];
#pragma unroll
        for (int k = 1; k < 8; ++k) tot += s_red[k];
        s_red[9] = 1.0f / tot;
    }
    __syncthreads();
    const float inv = s_red[9];
    if (tid < LL) s_logits[tid] = e * inv;     // probs
    __syncthreads();

    // ---- pass 2: out[h] = sum_l p[l] * hist[l][h]  (SMEM only) ----
    float4 a4 = {0.f, 0.f, 0.f, 0.f};
    const int l0 = warp * 25;
#pragma unroll
    for (int it = 0; it < 25; ++it) {
        const int l = l0 + it;
        const float sc = s_logits[l];
        float4 v = s_h4[l * 32 + lane];
        a4.x = fmaf(sc, v.x, a4.x);
        a4.y = fmaf(sc, v.y, a4.y);
        a4.z = fmaf(sc, v.z, a4.z);
        a4.w = fmaf(sc, v.w, a4.w);
    }
    s_part[warp * 32 + lane] = a4;
    __syncthreads();

    if (warp == 0) {
        float4 r = s_part[lane];
#pragma unroll
        for (int g = 1; g < 8; ++g) {
            float4 p = s_part[g * 32 + lane];
            r.x += p.x; r.y += p.y; r.z += p.z; r.w += p.w;
        }
        ((float4*)(out + (size_t)b * HH))[lane] = r;
    }
}

// ---------------------------------------------------------------------------
extern "C" void kernel_launch(void* const* d_in, const int* in_sizes, int n_in,
                              void* d_out, int out_size) {
    // Bind inputs BY ELEMENT COUNT (all four are distinct) — immune to ordering.
    const float* query = nullptr;   // 8192*128   = 1048576
    const float* hist  = nullptr;   // 8192*200*128 = 209715200
    const void*  hlen  = nullptr;   // 8192
    const float* W     = nullptr;   // 128*128    = 16384
    for (int i = 0; i < n_in; ++i) {
        switch (in_sizes[i]) {
            case BB * QQ:      query = (const float*)d_in[i]; break;
            case BB * LL * HH: hist  = (const float*)d_in[i]; break;
            case BB:           hlen  = d_in[i];               break;
            case QQ * HH:      W     = (const float*)d_in[i]; break;
            default: break;
        }
    }
    float* out = (float*)d_out;     // [B, H] float32

    const int smem1 = (QQ * HH + 64 * 132) * (int)sizeof(float);             // 99328 B
    const int smem2 = (LL * HH + 256 + 16 + 8 * 32 * 4) * (int)sizeof(float);// 107584 B

    cudaFuncSetAttribute(qw_gemm_kernel,
                         cudaFuncAttributeMaxDynamicSharedMemorySize, smem1);
    cudaFuncSetAttribute(attn_pool_kernel,
                         cudaFuncAttributeMaxDynamicSharedMemorySize, smem2);

    detect_len_dtype_kernel<<<1, 32>>>((const int*)hlen);
    qw_gemm_kernel<<<BB / 64, 256, smem1>>>(query, W);
    attn_pool_kernel<<<BB, 256, smem2>>>(hist, hlen, out);
}

// round 3
// speedup vs baseline: 1.0411x; 1.0411x over previous
#include <cuda_runtime.h>
#include <cstdint>

#define BB 8192
#define LL 200
#define QQ 128
#define HH 128
#define GRID 148
#define NTHREADS 512

#define ROW_FLOATS (LL * HH)          // 25600
#define ROW_BYTES  (ROW_FLOATS * 4)   // 102400

// qw scratch: qw[b][h] = sum_q query[b][q] * W[q][h]   (4 MB)
__device__ float g_qw[BB * HH];
__device__ int g_len_is64;

// ---------------------------------------------------------------------------
// PTX helpers
// ---------------------------------------------------------------------------
__device__ __forceinline__ uint32_t smem_u32(const void* p) {
    uint32_t a;
    asm("{ .reg .u64 t; cvta.to.shared.u64 t, %1; cvt.u32.u64 %0, t; }"
        : "=r"(a) : "l"(p));
    return a;
}
__device__ __forceinline__ void mbar_init(uint32_t mbar, uint32_t count) {
    asm volatile("mbarrier.init.shared.b64 [%0], %1;" :: "r"(mbar), "r"(count) : "memory");
}
__device__ __forceinline__ void mbar_expect_tx(uint32_t mbar, uint32_t bytes) {
    asm volatile("mbarrier.arrive.expect_tx.shared.b64 _, [%0], %1;"
                 :: "r"(mbar), "r"(bytes) : "memory");
}
__device__ __forceinline__ void bulk_g2s(uint32_t dst, const void* src,
                                         uint32_t bytes, uint32_t mbar) {
    asm volatile(
        "cp.async.bulk.shared::cta.global.mbarrier::complete_tx::bytes "
        "[%0], [%1], %2, [%3];"
        :: "r"(dst), "l"(src), "r"(bytes), "r"(mbar) : "memory");
}
__device__ __forceinline__ void mbar_wait(uint32_t mbar, uint32_t parity) {
    uint32_t done;
    asm volatile(
        "{\n .reg .pred p;\n"
        " mbarrier.try_wait.parity.acquire.cta.shared::cta.b64 p, [%1], %2, 0x989680;\n"
        " selp.b32 %0, 1, 0, p;\n}"
        : "=r"(done) : "r"(mbar), "r"(parity) : "memory");
    while (!done) {
        asm volatile(
            "{\n .reg .pred p;\n"
            " mbarrier.try_wait.parity.acquire.cta.shared::cta.b64 p, [%1], %2, 0x989680;\n"
            " selp.b32 %0, 1, 0, p;\n}"
            : "=r"(done) : "r"(mbar), "r"(parity) : "memory");
    }
}

// ---------------------------------------------------------------------------
// Kernel 1: qw = query @ W (register-tiled GEMM) + len-dtype detection
// grid = 128 CTAs, 256 threads, each CTA computes 64 rows of qw.
// ---------------------------------------------------------------------------
__global__ __launch_bounds__(256, 2) void qw_gemm_kernel(
    const float* __restrict__ query, const float* __restrict__ W,
    const int* __restrict__ len32)
{
    extern __shared__ float smem1[];
    float* sW = smem1;                 // [128][128]
    float* sQ = smem1 + QQ * HH;       // [64][132] padded

    const int tid = threadIdx.x;
    const int b0  = blockIdx.x * 64;

    // len dtype detection: int64 values in [0,200) -> all odd dwords zero
    if (blockIdx.x == 0 && tid == 0) {
        int nz = 0;
#pragma unroll
        for (int i = 1; i < 256; i += 2) nz += (len32[i] != 0);
        g_len_is64 = (nz == 0) ? 1 : 0;
    }

    const float4* W4 = (const float4*)W;
    float4* sW4 = (float4*)sW;
#pragma unroll
    for (int i = 0; i < 16; ++i)
        sW4[tid + i * 256] = W4[tid + i * 256];

    const float4* Q4 = (const float4*)(query + (size_t)b0 * QQ);
#pragma unroll
    for (int i = 0; i < 8; ++i) {
        int idx = tid + i * 256;
        int r = idx >> 5;
        int c = (idx & 31) << 2;
        float4 v = Q4[idx];
        *(float4*)&sQ[r * 132 + c] = v;
    }
    __syncthreads();

    const int j  = tid & 15;
    const int i  = tid >> 4;
    const int r0 = i * 4;
    const int h0 = j * 8;

    float acc[4][8];
#pragma unroll
    for (int a = 0; a < 4; ++a)
#pragma unroll
        for (int c = 0; c < 8; ++c) acc[a][c] = 0.f;

#pragma unroll 4
    for (int q = 0; q < QQ; ++q) {
        float4 w0 = *(const float4*)&sW[q * HH + h0];
        float4 w1 = *(const float4*)&sW[q * HH + h0 + 4];
        float wv[8] = {w0.x, w0.y, w0.z, w0.w, w1.x, w1.y, w1.z, w1.w};
        float qv[4];
#pragma unroll
        for (int a = 0; a < 4; ++a) qv[a] = sQ[(r0 + a) * 132 + q];
#pragma unroll
        for (int a = 0; a < 4; ++a)
#pragma unroll
            for (int c = 0; c < 8; ++c)
                acc[a][c] = fmaf(qv[a], wv[c], acc[a][c]);
    }

#pragma unroll
    for (int a = 0; a < 4; ++a) {
        float4 o0 = {acc[a][0], acc[a][1], acc[a][2], acc[a][3]};
        float4 o1 = {acc[a][4], acc[a][5], acc[a][6], acc[a][7]};
        float* dst = g_qw + (size_t)(b0 + r0 + a) * HH + h0;
        *(float4*)dst       = o0;
        *(float4*)(dst + 4) = o1;
    }
}

// ---------------------------------------------------------------------------
// Kernel 2: persistent, double-buffered attention pooling.
// grid=148 (1 CTA/SM), 512 threads. Each CTA loops over rows b = bid+148k.
// TMA bulk copy fills the inactive buffer while threads compute on the other.
//
// SMEM layout (floats):
//   buf0 [0,25600)   buf1 [25600,51200)
//   s_logits [51200,51456)   s_red [51456,51488)
//   s_part float4[16*32] @ 51488 (byte 205952, 16B aligned)
//   mbar  2 x u64 @ float 53536 (byte 214144)
// total 214160 B
// ---------------------------------------------------------------------------
__global__ __launch_bounds__(NTHREADS, 1) void attn_pool_kernel(
    const float* __restrict__ hist, const void* __restrict__ hlen,
    float* __restrict__ out)
{
    extern __shared__ float smem[];
    float*  bufs[2] = { smem, smem + ROW_FLOATS };
    float*  s_logits = smem + 2 * ROW_FLOATS;          // 51200
    float*  s_red    = s_logits + 256;                 // 51456
    float4* s_part   = (float4*)(s_red + 32);          // 51488
    uint64_t* mbar   = (uint64_t*)(smem + 53536);

    const int tid  = threadIdx.x;
    const int warp = tid >> 5;
    const int lane = tid & 31;
    const int bid  = blockIdx.x;

    const uint32_t mbar_a[2] = { smem_u32(&mbar[0]), smem_u32(&mbar[1]) };
    const uint32_t buf_a[2]  = { smem_u32(bufs[0]),  smem_u32(bufs[1])  };

    if (tid == 0) { mbar_init(mbar_a[0], 1); mbar_init(mbar_a[1], 1); }
    __syncthreads();

    const int is64 = g_len_is64;

    // prologue: kick off first row into buf0
    if (tid == 0) {
        mbar_expect_tx(mbar_a[0], ROW_BYTES);
        bulk_g2s(buf_a[0], hist + (size_t)bid * ROW_FLOATS, ROW_BYTES, mbar_a[0]);
    }

    uint32_t ph0 = 0, ph1 = 0;
    int it = 0;
    for (int b = bid; b < BB; b += GRID, ++it) {
        const int cur = it & 1;

        // issue next row into the other buffer (safe: fully consumed 1 iter ago)
        const int bn = b + GRID;
        if (bn < BB && tid == 0) {
            mbar_expect_tx(mbar_a[cur ^ 1], ROW_BYTES);
            bulk_g2s(buf_a[cur ^ 1], hist + (size_t)bn * ROW_FLOATS,
                     ROW_BYTES, mbar_a[cur ^ 1]);
        }

        // wait for current buffer
        if (cur == 0) { mbar_wait(mbar_a[0], ph0); ph0 ^= 1; }
        else          { mbar_wait(mbar_a[1], ph1); ph1 ^= 1; }

        const float4* s4 = (const float4*)bufs[cur];

        // qw fragment for this row
        const float4 qwv = ((const float4*)(g_qw + (size_t)b * HH))[lane];

        // ---- logits: warp w handles l = w, w+16, ... ----
        for (int l = warp; l < LL; l += 16) {
            float4 v = s4[l * 32 + lane];
            float p = v.x * qwv.x + v.y * qwv.y + v.z * qwv.z + v.w * qwv.w;
            p += __shfl_xor_sync(0xffffffffu, p, 16);
            p += __shfl_xor_sync(0xffffffffu, p, 8);
            p += __shfl_xor_sync(0xffffffffu, p, 4);
            p += __shfl_xor_sync(0xffffffffu, p, 2);
            p += __shfl_xor_sync(0xffffffffu, p, 1);
            if (lane == 0) s_logits[l] = p;
        }
        __syncthreads();

        // ---- mask + softmax ----
        long long Lb;
        if (is64) Lb = ((const long long*)hlen)[b];
        else      Lb = (long long)((const int*)hlen)[b];

        float lg = -1e30f;
        if (tid < LL) {
            lg = s_logits[tid];
            if ((long long)tid < Lb) lg = 1e-9f;   // faithful reference mask
        }

        float m = lg;
        m = fmaxf(m, __shfl_xor_sync(0xffffffffu, m, 16));
        m = fmaxf(m, __shfl_xor_sync(0xffffffffu, m, 8));
        m = fmaxf(m, __shfl_xor_sync(0xffffffffu, m, 4));
        m = fmaxf(m, __shfl_xor_sync(0xffffffffu, m, 2));
        m = fmaxf(m, __shfl_xor_sync(0xffffffffu, m, 1));
        if (lane == 0) s_red[warp] = m;
        __syncthreads();
        if (tid == 0) {
            float mm = s_red[0];
#pragma unroll
            for (int k = 1; k < 16; ++k) mm = fmaxf(mm, s_red[k]);
            s_red[16] = mm;
        }
        __syncthreads();
        const float mx = s_red[16];

        float e = (tid < LL) ? __expf(lg - mx) : 0.f;
        float s = e;
        s += __shfl_xor_sync(0xffffffffu, s, 16);
        s += __shfl_xor_sync(0xffffffffu, s, 8);
        s += __shfl_xor_sync(0xffffffffu, s, 4);
        s += __shfl_xor_sync(0xffffffffu, s, 2);
        s += __shfl_xor_sync(0xffffffffu, s, 1);
        __syncthreads();   // s_red[0..15] fully consumed above before reuse
        if (lane == 0) s_red[warp] = s;
        __syncthreads();
        if (tid == 0) {
            float tot = s_red[0];
#pragma unroll
            for (int k = 1; k < 16; ++k) tot += s_red[k];
            s_red[17] = 1.0f / tot;
        }
        __syncthreads();
        const float inv = s_red[17];
        if (tid < LL) s_logits[tid] = e * inv;   // probs
        __syncthreads();

        // ---- pass 2: out[h] = sum_l p[l]*hist[l][h] (SMEM only) ----
        float4 a4 = {0.f, 0.f, 0.f, 0.f};
        for (int l = warp; l < LL; l += 16) {
            const float sc = s_logits[l];
            float4 v = s4[l * 32 + lane];
            a4.x = fmaf(sc, v.x, a4.x);
            a4.y = fmaf(sc, v.y, a4.y);
            a4.z = fmaf(sc, v.z, a4.z);
            a4.w = fmaf(sc, v.w, a4.w);
        }
        s_part[warp * 32 + lane] = a4;
        __syncthreads();   // also guarantees all buf[cur] reads done

        if (warp == 0) {
            float4 r = s_part[lane];
#pragma unroll
            for (int g = 1; g < 16; ++g) {
                float4 p = s_part[g * 32 + lane];
                r.x += p.x; r.y += p.y; r.z += p.z; r.w += p.w;
            }
            ((float4*)(out + (size_t)b * HH))[lane] = r;
        }
    }
}

// ---------------------------------------------------------------------------
extern "C" void kernel_launch(void* const* d_in, const int* in_sizes, int n_in,
                              void* d_out, int out_size) {
    // Bind inputs BY ELEMENT COUNT (all distinct) — immune to ordering.
    const float* query = nullptr;   // 1048576
    const float* hist  = nullptr;   // 209715200
    const void*  hlen  = nullptr;   // 8192
    const float* W     = nullptr;   // 16384
    for (int i = 0; i < n_in; ++i) {
        switch (in_sizes[i]) {
            case BB * QQ:      query = (const float*)d_in[i]; break;
            case BB * LL * HH: hist  = (const float*)d_in[i]; break;
            case BB:           hlen  = d_in[i];               break;
            case QQ * HH:      W     = (const float*)d_in[i]; break;
            default: break;
        }
    }
    float* out = (float*)d_out;

    const int smem1 = (QQ * HH + 64 * 132) * (int)sizeof(float);   // 99328
    const int smem2 = 214160 + 48;                                  // 214208

    cudaFuncSetAttribute(qw_gemm_kernel,
                         cudaFuncAttributeMaxDynamicSharedMemorySize, smem1);
    cudaFuncSetAttribute(attn_pool_kernel,
                         cudaFuncAttributeMaxDynamicSharedMemorySize, smem2);

    qw_gemm_kernel<<<BB / 64, 256, smem1>>>(query, W, (const int*)hlen);
    attn_pool_kernel<<<GRID, NTHREADS, smem2>>>(hist, hlen, out);
}

// round 4
// speedup vs baseline: 1.3114x; 1.2596x over previous
#include <cuda_runtime.h>
#include <cstdint>

#define BB 8192
#define LL 200
#define QQ 128
#define HH 128
#define GRID 148
#define NTHREADS 512

#define ROW_FLOATS (LL * HH)          // 25600
#define ROW_BYTES  (ROW_FLOATS * 4)   // 102400

__device__ float g_qw[BB * HH];       // qw = query @ W   (4 MB)
__device__ int g_len_is64;

// ---------------------------------------------------------------------------
// PTX helpers
// ---------------------------------------------------------------------------
__device__ __forceinline__ uint32_t smem_u32(const void* p) {
    uint32_t a;
    asm("{ .reg .u64 t; cvta.to.shared.u64 t, %1; cvt.u32.u64 %0, t; }"
        : "=r"(a) : "l"(p));
    return a;
}
__device__ __forceinline__ void mbar_init(uint32_t mbar, uint32_t count) {
    asm volatile("mbarrier.init.shared.b64 [%0], %1;" :: "r"(mbar), "r"(count) : "memory");
}
__device__ __forceinline__ void mbar_expect_tx(uint32_t mbar, uint32_t bytes) {
    asm volatile("mbarrier.arrive.expect_tx.shared.b64 _, [%0], %1;"
                 :: "r"(mbar), "r"(bytes) : "memory");
}
__device__ __forceinline__ void bulk_g2s(uint32_t dst, const void* src,
                                         uint32_t bytes, uint32_t mbar) {
    asm volatile(
        "cp.async.bulk.shared::cta.global.mbarrier::complete_tx::bytes "
        "[%0], [%1], %2, [%3];"
        :: "r"(dst), "l"(src), "r"(bytes), "r"(mbar) : "memory");
}
__device__ __forceinline__ void mbar_wait(uint32_t mbar, uint32_t parity) {
    uint32_t done;
    asm volatile(
        "{\n .reg .pred p;\n"
        " mbarrier.try_wait.parity.acquire.cta.shared::cta.b64 p, [%1], %2, 0x989680;\n"
        " selp.b32 %0, 1, 0, p;\n}"
        : "=r"(done) : "r"(mbar), "r"(parity) : "memory");
    while (!done) {
        asm volatile(
            "{\n .reg .pred p;\n"
            " mbarrier.try_wait.parity.acquire.cta.shared::cta.b64 p, [%1], %2, 0x989680;\n"
            " selp.b32 %0, 1, 0, p;\n}"
            : "=r"(done) : "r"(mbar), "r"(parity) : "memory");
    }
}

// ---------------------------------------------------------------------------
// Kernel 1: qw = query @ W (register-tiled GEMM) + len-dtype detection
// ---------------------------------------------------------------------------
__global__ __launch_bounds__(256, 2) void qw_gemm_kernel(
    const float* __restrict__ query, const float* __restrict__ W,
    const int* __restrict__ len32)
{
    extern __shared__ float smem1[];
    float* sW = smem1;                 // [128][128]
    float* sQ = smem1 + QQ * HH;       // [64][132] padded

    const int tid = threadIdx.x;
    const int b0  = blockIdx.x * 64;

    // len dtype detection: int64 values in [0,200) -> all odd dwords zero
    if (blockIdx.x == 0 && tid == 0) {
        int nz = 0;
#pragma unroll
        for (int i = 1; i < 256; i += 2) nz += (len32[i] != 0);
        g_len_is64 = (nz == 0) ? 1 : 0;
    }

    const float4* W4 = (const float4*)W;
    float4* sW4 = (float4*)sW;
#pragma unroll
    for (int i = 0; i < 16; ++i)
        sW4[tid + i * 256] = W4[tid + i * 256];

    const float4* Q4 = (const float4*)(query + (size_t)b0 * QQ);
#pragma unroll
    for (int i = 0; i < 8; ++i) {
        int idx = tid + i * 256;
        int r = idx >> 5;
        int c = (idx & 31) << 2;
        float4 v = Q4[idx];
        *(float4*)&sQ[r * 132 + c] = v;
    }
    __syncthreads();

    const int j  = tid & 15;
    const int i  = tid >> 4;
    const int r0 = i * 4;
    const int h0 = j * 8;

    float acc[4][8];
#pragma unroll
    for (int a = 0; a < 4; ++a)
#pragma unroll
        for (int c = 0; c < 8; ++c) acc[a][c] = 0.f;

#pragma unroll 4
    for (int q = 0; q < QQ; ++q) {
        float4 w0 = *(const float4*)&sW[q * HH + h0];
        float4 w1 = *(const float4*)&sW[q * HH + h0 + 4];
        float wv[8] = {w0.x, w0.y, w0.z, w0.w, w1.x, w1.y, w1.z, w1.w};
        float qv[4];
#pragma unroll
        for (int a = 0; a < 4; ++a) qv[a] = sQ[(r0 + a) * 132 + q];
#pragma unroll
        for (int a = 0; a < 4; ++a)
#pragma unroll
            for (int c = 0; c < 8; ++c)
                acc[a][c] = fmaf(qv[a], wv[c], acc[a][c]);
    }

#pragma unroll
    for (int a = 0; a < 4; ++a) {
        float4 o0 = {acc[a][0], acc[a][1], acc[a][2], acc[a][3]};
        float4 o1 = {acc[a][4], acc[a][5], acc[a][6], acc[a][7]};
        float* dst = g_qw + (size_t)(b0 + r0 + a) * HH + h0;
        *(float4*)dst       = o0;
        *(float4*)(dst + 4) = o1;
    }
}

// ---------------------------------------------------------------------------
// Kernel 2: persistent, double-buffered attention pooling.
// grid=148 (1 CTA/SM), 512 threads, depth-2 TMA pipeline.
//
// SMEM layout (floats):
//   buf0 [0,25600)   buf1 [25600,51200)
//   s_logits [51200,51456)
//   s_part float4[16*32] @ 51456 (byte 205824, 16B aligned)
//   mbar 2 x u64 @ float 53504
// ---------------------------------------------------------------------------
__global__ __launch_bounds__(NTHREADS, 1) void attn_pool_kernel(
    const float* __restrict__ hist, const void* __restrict__ hlen,
    float* __restrict__ out)
{
    extern __shared__ float smem[];
    float*  bufs[2] = { smem, smem + ROW_FLOATS };
    float*  s_logits = smem + 2 * ROW_FLOATS;          // 51200
    float4* s_part   = (float4*)(s_logits + 256);      // 51456
    uint64_t* mbar   = (uint64_t*)(smem + 53504);

    const int tid  = threadIdx.x;
    const int warp = tid >> 5;
    const int lane = tid & 31;
    const int bid  = blockIdx.x;
    const int k    = lane & 7;      // column octet (0..7)
    const int r    = lane >> 3;     // row-in-group (0..3)

    const uint32_t mbar_a[2] = { smem_u32(&mbar[0]), smem_u32(&mbar[1]) };
    const uint32_t buf_a[2]  = { smem_u32(bufs[0]),  smem_u32(bufs[1])  };

    if (tid == 0) { mbar_init(mbar_a[0], 1); mbar_init(mbar_a[1], 1); }
    __syncthreads();

    const int is64 = g_len_is64;

    // prologue: first row into buf0
    if (tid == 0) {
        mbar_expect_tx(mbar_a[0], ROW_BYTES);
        bulk_g2s(buf_a[0], hist + (size_t)bid * ROW_FLOATS, ROW_BYTES, mbar_a[0]);
    }

    uint32_t ph0 = 0, ph1 = 0;
    int it = 0;
    for (int b = bid; b < BB; b += GRID, ++it) {
        const int cur = it & 1;

        // issue next row into the other buffer (its data was consumed last iter)
        const int bn = b + GRID;
        if (bn < BB && tid == 0) {
            mbar_expect_tx(mbar_a[cur ^ 1], ROW_BYTES);
            bulk_g2s(buf_a[cur ^ 1], hist + (size_t)bn * ROW_FLOATS,
                     ROW_BYTES, mbar_a[cur ^ 1]);
        }

        // qw fragment: lane needs qw[b][ (c*8+k)*4 .. +3 ] for c=0..3
        const float4* qw4 = (const float4*)(g_qw + (size_t)b * HH);
        float4 qv[4];
#pragma unroll
        for (int c = 0; c < 4; ++c) qv[c] = qw4[c * 8 + k];

        // wait for current buffer
        if (cur == 0) { mbar_wait(mbar_a[0], ph0); ph0 ^= 1; }
        else          { mbar_wait(mbar_a[1], ph1); ph1 ^= 1; }

        const float4* s4 = (const float4*)bufs[cur];

        // ---- pass 1: logits. 4 rows per warp-iteration (50 groups of 4). ----
        // lane (r,k): row g*4+r, float4 cols {c*8+k}. Each 8-lane wavefront
        // reads contiguous 128B -> conflict-free. 3 SHFLs per 4 rows.
        for (int g = warp; g < 50; g += 16) {
            const int l = g * 4 + r;
            const float4* row4 = s4 + l * 32;
            float p = 0.f;
#pragma unroll
            for (int c = 0; c < 4; ++c) {
                float4 v = row4[c * 8 + k];
                p += v.x * qv[c].x + v.y * qv[c].y + v.z * qv[c].z + v.w * qv[c].w;
            }
            p += __shfl_xor_sync(0xffffffffu, p, 4);
            p += __shfl_xor_sync(0xffffffffu, p, 2);
            p += __shfl_xor_sync(0xffffffffu, p, 1);
            if (k == 0) s_logits[l] = p;
        }
        __syncthreads();

        // ---- softmax: single warp holds all 200 logits in registers ----
        if (warp == 0) {
            long long Lb;
            if (is64) Lb = ((const long long*)hlen)[b];
            else      Lb = (long long)((const int*)hlen)[b];

            float v[7];
#pragma unroll
            for (int j = 0; j < 7; ++j) {
                const int l = lane + j * 32;
                float x = -1e30f;
                if (l < LL) {
                    x = s_logits[l];
                    if ((long long)l < Lb) x = 1e-9f;   // faithful reference mask
                }
                v[j] = x;
            }
            float m = v[0];
#pragma unroll
            for (int j = 1; j < 7; ++j) m = fmaxf(m, v[j]);
            m = fmaxf(m, __shfl_xor_sync(0xffffffffu, m, 16));
            m = fmaxf(m, __shfl_xor_sync(0xffffffffu, m, 8));
            m = fmaxf(m, __shfl_xor_sync(0xffffffffu, m, 4));
            m = fmaxf(m, __shfl_xor_sync(0xffffffffu, m, 2));
            m = fmaxf(m, __shfl_xor_sync(0xffffffffu, m, 1));

            float s = 0.f;
#pragma unroll
            for (int j = 0; j < 7; ++j) {
                v[j] = __expf(v[j] - m);   // OOR lanes: exp(-huge)=0
                s += v[j];
            }
            s += __shfl_xor_sync(0xffffffffu, s, 16);
            s += __shfl_xor_sync(0xffffffffu, s, 8);
            s += __shfl_xor_sync(0xffffffffu, s, 4);
            s += __shfl_xor_sync(0xffffffffu, s, 2);
            s += __shfl_xor_sync(0xffffffffu, s, 1);
            const float inv = 1.0f / s;
#pragma unroll
            for (int j = 0; j < 7; ++j) {
                const int l = lane + j * 32;
                if (l < LL) s_logits[l] = v[j] * inv;
            }
        }
        __syncthreads();

        // ---- pass 2: out[h] = sum_l p[l]*hist[l][h] (SMEM only) ----
        float4 a4 = {0.f, 0.f, 0.f, 0.f};
        for (int l = warp; l < LL; l += 16) {
            const float sc = s_logits[l];
            float4 v = s4[l * 32 + lane];
            a4.x = fmaf(sc, v.x, a4.x);
            a4.y = fmaf(sc, v.y, a4.y);
            a4.z = fmaf(sc, v.z, a4.z);
            a4.w = fmaf(sc, v.w, a4.w);
        }
        s_part[warp * 32 + lane] = a4;
        __syncthreads();   // all buf[cur] reads done after this

        if (warp == 0) {
            float4 rr = s_part[lane];
#pragma unroll
            for (int g = 1; g < 16; ++g) {
                float4 p = s_part[g * 32 + lane];
                rr.x += p.x; rr.y += p.y; rr.z += p.z; rr.w += p.w;
            }
            ((float4*)(out + (size_t)b * HH))[lane] = rr;
        }
    }
}

// ---------------------------------------------------------------------------
extern "C" void kernel_launch(void* const* d_in, const int* in_sizes, int n_in,
                              void* d_out, int out_size) {
    // Bind inputs BY ELEMENT COUNT (all distinct) — immune to ordering.
    const float* query = nullptr;   // 1048576
    const float* hist  = nullptr;   // 209715200
    const void*  hlen  = nullptr;   // 8192
    const float* W     = nullptr;   // 16384
    for (int i = 0; i < n_in; ++i) {
        switch (in_sizes[i]) {
            case BB * QQ:      query = (const float*)d_in[i]; break;
            case BB * LL * HH: hist  = (const float*)d_in[i]; break;
            case BB:           hlen  = d_in[i];               break;
            case QQ * HH:      W     = (const float*)d_in[i]; break;
            default: break;
        }
    }
    float* out = (float*)d_out;

    const int smem1 = (QQ * HH + 64 * 132) * (int)sizeof(float);   // 99328
    const int smem2 = 53504 * 4 + 64;                               // 214080

    cudaFuncSetAttribute(qw_gemm_kernel,
                         cudaFuncAttributeMaxDynamicSharedMemorySize, smem1);
    cudaFuncSetAttribute(attn_pool_kernel,
                         cudaFuncAttributeMaxDynamicSharedMemorySize, smem2);

    qw_gemm_kernel<<<BB / 64, 256, smem1>>>(query, W, (const int*)hlen);
    attn_pool_kernel<<<GRID, NTHREADS, smem2>>>(hist, hlen, out);
}

// round 5
// speedup vs baseline: 1.4863x; 1.1334x over previous
#include <cuda_runtime.h>
#include <cstdint>

#define BB 8192
#define LL 200
#define QQ 128
#define HH 128
#define GRID 148
#define NTHREADS 512

#define ROW_FLOATS (LL * HH)          // 25600
#define ROW_BYTES  (ROW_FLOATS * 4)   // 102400

__device__ float g_qw[BB * HH];       // qw = query @ W   (4 MB)
__device__ int g_len_is64;

// ---------------------------------------------------------------------------
// PTX helpers
// ---------------------------------------------------------------------------
__device__ __forceinline__ uint32_t smem_u32(const void* p) {
    uint32_t a;
    asm("{ .reg .u64 t; cvta.to.shared.u64 t, %1; cvt.u32.u64 %0, t; }"
        : "=r"(a) : "l"(p));
    return a;
}
__device__ __forceinline__ void mbar_init(uint32_t mbar, uint32_t count) {
    asm volatile("mbarrier.init.shared.b64 [%0], %1;" :: "r"(mbar), "r"(count) : "memory");
}
__device__ __forceinline__ void mbar_expect_tx(uint32_t mbar, uint32_t bytes) {
    asm volatile("mbarrier.arrive.expect_tx.shared.b64 _, [%0], %1;"
                 :: "r"(mbar), "r"(bytes) : "memory");
}
__device__ __forceinline__ void bulk_g2s(uint32_t dst, const void* src,
                                         uint32_t bytes, uint32_t mbar) {
    asm volatile(
        "cp.async.bulk.shared::cta.global.mbarrier::complete_tx::bytes "
        "[%0], [%1], %2, [%3];"
        :: "r"(dst), "l"(src), "r"(bytes), "r"(mbar) : "memory");
}
__device__ __forceinline__ void mbar_wait(uint32_t mbar, uint32_t parity) {
    uint32_t done;
    asm volatile(
        "{\n .reg .pred p;\n"
        " mbarrier.try_wait.parity.acquire.cta.shared::cta.b64 p, [%1], %2, 0x989680;\n"
        " selp.b32 %0, 1, 0, p;\n}"
        : "=r"(done) : "r"(mbar), "r"(parity) : "memory");
    while (!done) {
        asm volatile(
            "{\n .reg .pred p;\n"
            " mbarrier.try_wait.parity.acquire.cta.shared::cta.b64 p, [%1], %2, 0x989680;\n"
            " selp.b32 %0, 1, 0, p;\n}"
            : "=r"(done) : "r"(mbar), "r"(parity) : "memory");
    }
}

// ---------------------------------------------------------------------------
// Kernel 1: qw = query @ W (register-tiled GEMM) + len-dtype detection
// ---------------------------------------------------------------------------
__global__ __launch_bounds__(256, 2) void qw_gemm_kernel(
    const float* __restrict__ query, const float* __restrict__ W,
    const int* __restrict__ len32)
{
    extern __shared__ float smem1[];
    float* sW = smem1;                 // [128][128]
    float* sQ = smem1 + QQ * HH;       // [64][132] padded

    const int tid = threadIdx.x;
    const int b0  = blockIdx.x * 64;

    // len dtype detection: int64 values in [0,200) -> all odd dwords zero
    if (blockIdx.x == 0 && tid == 0) {
        int nz = 0;
#pragma unroll
        for (int i = 1; i < 256; i += 2) nz += (len32[i] != 0);
        g_len_is64 = (nz == 0) ? 1 : 0;
    }

    const float4* W4 = (const float4*)W;
    float4* sW4 = (float4*)sW;
#pragma unroll
    for (int i = 0; i < 16; ++i)
        sW4[tid + i * 256] = W4[tid + i * 256];

    const float4* Q4 = (const float4*)(query + (size_t)b0 * QQ);
#pragma unroll
    for (int i = 0; i < 8; ++i) {
        int idx = tid + i * 256;
        int r = idx >> 5;
        int c = (idx & 31) << 2;
        float4 v = Q4[idx];
        *(float4*)&sQ[r * 132 + c] = v;
    }
    __syncthreads();

    const int j  = tid & 15;
    const int i  = tid >> 4;
    const int r0 = i * 4;
    const int h0 = j * 8;

    float acc[4][8];
#pragma unroll
    for (int a = 0; a < 4; ++a)
#pragma unroll
        for (int c = 0; c < 8; ++c) acc[a][c] = 0.f;

#pragma unroll 4
    for (int q = 0; q < QQ; ++q) {
        float4 w0 = *(const float4*)&sW[q * HH + h0];
        float4 w1 = *(const float4*)&sW[q * HH + h0 + 4];
        float wv[8] = {w0.x, w0.y, w0.z, w0.w, w1.x, w1.y, w1.z, w1.w};
        float qv[4];
#pragma unroll
        for (int a = 0; a < 4; ++a) qv[a] = sQ[(r0 + a) * 132 + q];
#pragma unroll
        for (int a = 0; a < 4; ++a)
#pragma unroll
            for (int c = 0; c < 8; ++c)
                acc[a][c] = fmaf(qv[a], wv[c], acc[a][c]);
    }

#pragma unroll
    for (int a = 0; a < 4; ++a) {
        float4 o0 = {acc[a][0], acc[a][1], acc[a][2], acc[a][3]};
        float4 o1 = {acc[a][4], acc[a][5], acc[a][6], acc[a][7]};
        float* dst = g_qw + (size_t)(b0 + r0 + a) * HH + h0;
        *(float4*)dst       = o0;
        *(float4*)(dst + 4) = o1;
    }
}

// ---------------------------------------------------------------------------
// Kernel 2: persistent, double-buffered attention pooling (no-max softmax,
// mask-skipped logits, 2 barriers/row).
// grid=148 (1 CTA/SM), 512 threads.
//
// SMEM (floats): buf0 [0,25600) | buf1 [25600,51200) | s_logits 51200..51456
//   s_red [51456,51472) | s_part float4[16*32] @ 51472 | mbar @ 53520
// ---------------------------------------------------------------------------
__global__ __launch_bounds__(NTHREADS, 1) void attn_pool_kernel(
    const float* __restrict__ hist, const void* __restrict__ hlen,
    float* __restrict__ out)
{
    extern __shared__ float smem[];
    float*  bufs[2] = { smem, smem + ROW_FLOATS };
    float*  s_logits = smem + 2 * ROW_FLOATS;          // 51200 (holds exp(logit))
    float*  s_red    = s_logits + 256;                 // 51456 (16 warp sums)
    float4* s_part   = (float4*)(s_red + 16);          // 51472 (byte 205888, 16B ok)
    uint64_t* mbar   = (uint64_t*)(smem + 53520);

    const int tid  = threadIdx.x;
    const int warp = tid >> 5;
    const int lane = tid & 31;
    const int bid  = blockIdx.x;
    const int k    = lane & 7;      // column octet (0..7)
    const int r    = lane >> 3;     // row-in-group (0..3)

    const uint32_t mbar_a[2] = { smem_u32(&mbar[0]), smem_u32(&mbar[1]) };
    const uint32_t buf_a[2]  = { smem_u32(bufs[0]),  smem_u32(bufs[1])  };

    if (tid == 0) { mbar_init(mbar_a[0], 1); mbar_init(mbar_a[1], 1); }
    __syncthreads();

    const int is64 = g_len_is64;

    // prologue: first row into buf0
    if (tid == 0) {
        mbar_expect_tx(mbar_a[0], ROW_BYTES);
        bulk_g2s(buf_a[0], hist + (size_t)bid * ROW_FLOATS, ROW_BYTES, mbar_a[0]);
    }

    uint32_t ph0 = 0, ph1 = 0;
    int it = 0;
    for (int b = bid; b < BB; b += GRID, ++it) {
        const int cur = it & 1;

        // issue next row into the other buffer (fully consumed last iter)
        const int bn = b + GRID;
        if (bn < BB && tid == 0) {
            mbar_expect_tx(mbar_a[cur ^ 1], ROW_BYTES);
            bulk_g2s(buf_a[cur ^ 1], hist + (size_t)bn * ROW_FLOATS,
                     ROW_BYTES, mbar_a[cur ^ 1]);
        }

        // prefetch qw fragment + length while TMA runs
        const float4* qw4 = (const float4*)(g_qw + (size_t)b * HH);
        float4 qv[4];
#pragma unroll
        for (int c = 0; c < 4; ++c) qv[c] = qw4[c * 8 + k];

        int Lb;
        if (is64) Lb = (int)((const long long*)hlen)[b];
        else      Lb = ((const int*)hlen)[b];

        // wait for current buffer
        if (cur == 0) { mbar_wait(mbar_a[0], ph0); ph0 ^= 1; }
        else          { mbar_wait(mbar_a[1], ph1); ph1 ^= 1; }

        const float4* s4 = (const float4*)bufs[cur];

        // ---- pass 1: e_l = exp(logit_l) (no max-sub; masked rows -> 1.0f).
        // 4 rows/group, 8 lanes/row. Fully-masked groups (4g+3 < Lb) skip the
        // dot entirely (group index g is warp-uniform -> no divergence).
        float wsum = 0.f;
        for (int g = warp; g < 50; g += 16) {
            const int l = g * 4 + r;
            float e = 1.0f;                      // expf(1e-9f) == 1.0f
            if (g * 4 + 3 >= Lb) {               // group has unmasked rows
                const float4* row4 = s4 + l * 32;
                float p = 0.f;
#pragma unroll
                for (int c = 0; c < 4; ++c) {
                    float4 v = row4[c * 8 + k];
                    p += v.x * qv[c].x + v.y * qv[c].y + v.z * qv[c].z + v.w * qv[c].w;
                }
                p += __shfl_xor_sync(0xffffffffu, p, 4);
                p += __shfl_xor_sync(0xffffffffu, p, 2);
                p += __shfl_xor_sync(0xffffffffu, p, 1);
                if (l >= Lb) e = __expf(p);
            }
            if (k == 0) { s_logits[l] = e; wsum += e; }
        }
        // combine the 4 k==0 lanes (0,8,16,24)
        wsum += __shfl_xor_sync(0xffffffffu, wsum, 16);
        wsum += __shfl_xor_sync(0xffffffffu, wsum, 8);
        if (lane == 0) s_red[warp] = wsum;
        __syncthreads();

        // every thread privately computes 1/total (16 broadcast LDS, no barrier)
        float tot = 0.f;
#pragma unroll
        for (int w = 0; w < 16; ++w) tot += s_red[w];
        const float inv = __frcp_rn(tot);

        // ---- pass 2: out[h] = inv * sum_l e_l * hist[l][h] (SMEM only) ----
        float4 a4 = {0.f, 0.f, 0.f, 0.f};
        for (int l = warp; l < LL; l += 16) {
            const float sc = s_logits[l];
            float4 v = s4[l * 32 + lane];
            a4.x = fmaf(sc, v.x, a4.x);
            a4.y = fmaf(sc, v.y, a4.y);
            a4.z = fmaf(sc, v.z, a4.z);
            a4.w = fmaf(sc, v.w, a4.w);
        }
        a4.x *= inv; a4.y *= inv; a4.z *= inv; a4.w *= inv;
        s_part[warp * 32 + lane] = a4;
        __syncthreads();   // all buf[cur] reads done after this

        if (warp == 0) {
            float4 rr = s_part[lane];
#pragma unroll
            for (int g = 1; g < 16; ++g) {
                float4 p = s_part[g * 32 + lane];
                rr.x += p.x; rr.y += p.y; rr.z += p.z; rr.w += p.w;
            }
            ((float4*)(out + (size_t)b * HH))[lane] = rr;
        }
    }
}

// ---------------------------------------------------------------------------
extern "C" void kernel_launch(void* const* d_in, const int* in_sizes, int n_in,
                              void* d_out, int out_size) {
    // Bind inputs BY ELEMENT COUNT (all distinct) — immune to ordering.
    const float* query = nullptr;   // 1048576
    const float* hist  = nullptr;   // 209715200
    const void*  hlen  = nullptr;   // 8192
    const float* W     = nullptr;   // 16384
    for (int i = 0; i < n_in; ++i) {
        switch (in_sizes[i]) {
            case BB * QQ:      query = (const float*)d_in[i]; break;
            case BB * LL * HH: hist  = (const float*)d_in[i]; break;
            case BB:           hlen  = d_in[i];               break;
            case QQ * HH:      W     = (const float*)d_in[i]; break;
            default: break;
        }
    }
    float* out = (float*)d_out;

    const int smem1 = (QQ * HH + 64 * 132) * (int)sizeof(float);   // 99328
    const int smem2 = 53520 * 4 + 64;                               // 214144

    cudaFuncSetAttribute(qw_gemm_kernel,
                         cudaFuncAttributeMaxDynamicSharedMemorySize, smem1);
    cudaFuncSetAttribute(attn_pool_kernel,
                         cudaFuncAttributeMaxDynamicSharedMemorySize, smem2);

    qw_gemm_kernel<<<BB / 64, 256, smem1>>>(query, W, (const int*)hlen);
    attn_pool_kernel<<<GRID, NTHREADS, smem2>>>(hist, hlen, out);
}

// round 6
// speedup vs baseline: 1.5021x; 1.0107x over previous
#include <cuda_runtime.h>
#include <cstdint>

#define BB 8192
#define LL 200
#define QQ 128
#define HH 128
#define GRID 148
#define NTHREADS 512

#define ROW_FLOATS (LL * HH)          // 25600
#define ROW_BYTES  (ROW_FLOATS * 4)   // 102400

__device__ float g_qw[BB * HH];       // qw = query @ W   (4 MB)
__device__ int g_len_is64;

// ---------------------------------------------------------------------------
// PTX helpers
// ---------------------------------------------------------------------------
__device__ __forceinline__ uint32_t smem_u32(const void* p) {
    uint32_t a;
    asm("{ .reg .u64 t; cvta.to.shared.u64 t, %1; cvt.u32.u64 %0, t; }"
        : "=r"(a) : "l"(p));
    return a;
}
__device__ __forceinline__ void mbar_init(uint32_t mbar, uint32_t count) {
    asm volatile("mbarrier.init.shared.b64 [%0], %1;" :: "r"(mbar), "r"(count) : "memory");
}
__device__ __forceinline__ void mbar_expect_tx(uint32_t mbar, uint32_t bytes) {
    asm volatile("mbarrier.arrive.expect_tx.shared.b64 _, [%0], %1;"
                 :: "r"(mbar), "r"(bytes) : "memory");
}
__device__ __forceinline__ void bulk_g2s(uint32_t dst, const void* src,
                                         uint32_t bytes, uint32_t mbar) {
    asm volatile(
        "cp.async.bulk.shared::cta.global.mbarrier::complete_tx::bytes "
        "[%0], [%1], %2, [%3];"
        :: "r"(dst), "l"(src), "r"(bytes), "r"(mbar) : "memory");
}
__device__ __forceinline__ void mbar_wait(uint32_t mbar, uint32_t parity) {
    uint32_t done;
    asm volatile(
        "{\n .reg .pred p;\n"
        " mbarrier.try_wait.parity.acquire.cta.shared::cta.b64 p, [%1], %2, 0x989680;\n"
        " selp.b32 %0, 1, 0, p;\n}"
        : "=r"(done) : "r"(mbar), "r"(parity) : "memory");
    while (!done) {
        asm volatile(
            "{\n .reg .pred p;\n"
            " mbarrier.try_wait.parity.acquire.cta.shared::cta.b64 p, [%1], %2, 0x989680;\n"
            " selp.b32 %0, 1, 0, p;\n}"
            : "=r"(done) : "r"(mbar), "r"(parity) : "memory");
    }
}

// ---------------------------------------------------------------------------
// Kernel 1: qw = query @ W (register-tiled GEMM) + len-dtype detection
// ---------------------------------------------------------------------------
__global__ __launch_bounds__(256, 2) void qw_gemm_kernel(
    const float* __restrict__ query, const float* __restrict__ W,
    const int* __restrict__ len32)
{
    extern __shared__ float smem1[];
    float* sW = smem1;                 // [128][128]
    float* sQ = smem1 + QQ * HH;       // [64][132] padded

    const int tid = threadIdx.x;
    const int b0  = blockIdx.x * 64;

    // len dtype detection: int64 values in [0,200) -> all odd dwords zero
    if (blockIdx.x == 0 && tid == 0) {
        int nz = 0;
#pragma unroll
        for (int i = 1; i < 256; i += 2) nz += (len32[i] != 0);
        g_len_is64 = (nz == 0) ? 1 : 0;
    }

    const float4* W4 = (const float4*)W;
    float4* sW4 = (float4*)sW;
#pragma unroll
    for (int i = 0; i < 16; ++i)
        sW4[tid + i * 256] = W4[tid + i * 256];

    const float4* Q4 = (const float4*)(query + (size_t)b0 * QQ);
#pragma unroll
    for (int i = 0; i < 8; ++i) {
        int idx = tid + i * 256;
        int r = idx >> 5;
        int c = (idx & 31) << 2;
        float4 v = Q4[idx];
        *(float4*)&sQ[r * 132 + c] = v;
    }
    __syncthreads();

    const int j  = tid & 15;
    const int i  = tid >> 4;
    const int r0 = i * 4;
    const int h0 = j * 8;

    float acc[4][8];
#pragma unroll
    for (int a = 0; a < 4; ++a)
#pragma unroll
        for (int c = 0; c < 8; ++c) acc[a][c] = 0.f;

#pragma unroll 4
    for (int q = 0; q < QQ; ++q) {
        float4 w0 = *(const float4*)&sW[q * HH + h0];
        float4 w1 = *(const float4*)&sW[q * HH + h0 + 4];
        float wv[8] = {w0.x, w0.y, w0.z, w0.w, w1.x, w1.y, w1.z, w1.w};
        float qv[4];
#pragma unroll
        for (int a = 0; a < 4; ++a) qv[a] = sQ[(r0 + a) * 132 + q];
#pragma unroll
        for (int a = 0; a < 4; ++a)
#pragma unroll
            for (int c = 0; c < 8; ++c)
                acc[a][c] = fmaf(qv[a], wv[c], acc[a][c]);
    }

#pragma unroll
    for (int a = 0; a < 4; ++a) {
        float4 o0 = {acc[a][0], acc[a][1], acc[a][2], acc[a][3]};
        float4 o1 = {acc[a][4], acc[a][5], acc[a][6], acc[a][7]};
        float* dst = g_qw + (size_t)(b0 + r0 + a) * HH + h0;
        *(float4*)dst       = o0;
        *(float4*)(dst + 4) = o1;
    }
}

// ---------------------------------------------------------------------------
// Kernel 2: persistent, double-buffered attention pooling (no-max softmax,
// mask-skipped logits, 2 barriers/row).
// grid=148 (1 CTA/SM), 512 threads.
//
// SMEM (floats): buf0 [0,25600) | buf1 [25600,51200) | s_logits 51200..51456
//   s_red [51456,51472) | s_part float4[16*32] @ 51472 | mbar @ 53520
// ---------------------------------------------------------------------------
__global__ __launch_bounds__(NTHREADS, 1) void attn_pool_kernel(
    const float* __restrict__ hist, const void* __restrict__ hlen,
    float* __restrict__ out)
{
    extern __shared__ float smem[];
    float*  bufs[2] = { smem, smem + ROW_FLOATS };
    float*  s_logits = smem + 2 * ROW_FLOATS;          // 51200 (holds exp(logit))
    float*  s_red    = s_logits + 256;                 // 51456 (16 warp sums)
    float4* s_part   = (float4*)(s_red + 16);          // 51472 (byte 205888, 16B ok)
    uint64_t* mbar   = (uint64_t*)(smem + 53520);

    const int tid  = threadIdx.x;
    const int warp = tid >> 5;
    const int lane = tid & 31;
    const int bid  = blockIdx.x;
    const int k    = lane & 7;      // column octet (0..7)
    const int r    = lane >> 3;     // row-in-group (0..3)

    const uint32_t mbar_a[2] = { smem_u32(&mbar[0]), smem_u32(&mbar[1]) };
    const uint32_t buf_a[2]  = { smem_u32(bufs[0]),  smem_u32(bufs[1])  };

    if (tid == 0) { mbar_init(mbar_a[0], 1); mbar_init(mbar_a[1], 1); }
    __syncthreads();

    const int is64 = g_len_is64;

    // prologue: first row into buf0
    if (tid == 0) {
        mbar_expect_tx(mbar_a[0], ROW_BYTES);
        bulk_g2s(buf_a[0], hist + (size_t)bid * ROW_FLOATS, ROW_BYTES, mbar_a[0]);
    }

    uint32_t ph0 = 0, ph1 = 0;
    int it = 0;
    for (int b = bid; b < BB; b += GRID, ++it) {
        const int cur = it & 1;

        // issue next row into the other buffer (fully consumed last iter)
        const int bn = b + GRID;
        if (bn < BB && tid == 0) {
            mbar_expect_tx(mbar_a[cur ^ 1], ROW_BYTES);
            bulk_g2s(buf_a[cur ^ 1], hist + (size_t)bn * ROW_FLOATS,
                     ROW_BYTES, mbar_a[cur ^ 1]);
        }

        // prefetch qw fragment + length while TMA runs
        const float4* qw4 = (const float4*)(g_qw + (size_t)b * HH);
        float4 qv[4];
#pragma unroll
        for (int c = 0; c < 4; ++c) qv[c] = qw4[c * 8 + k];

        int Lb;
        if (is64) Lb = (int)((const long long*)hlen)[b];
        else      Lb = ((const int*)hlen)[b];

        // wait for current buffer
        if (cur == 0) { mbar_wait(mbar_a[0], ph0); ph0 ^= 1; }
        else          { mbar_wait(mbar_a[1], ph1); ph1 ^= 1; }

        const float4* s4 = (const float4*)bufs[cur];

        // ---- pass 1: e_l = exp(logit_l) (no max-sub; masked rows -> 1.0f).
        // 4 rows/group, 8 lanes/row. Fully-masked groups (4g+3 < Lb) skip the
        // dot entirely (group index g is warp-uniform -> no divergence).
        float wsum = 0.f;
        for (int g = warp; g < 50; g += 16) {
            const int l = g * 4 + r;
            float e = 1.0f;                      // expf(1e-9f) == 1.0f
            if (g * 4 + 3 >= Lb) {               // group has unmasked rows
                const float4* row4 = s4 + l * 32;
                float p = 0.f;
#pragma unroll
                for (int c = 0; c < 4; ++c) {
                    float4 v = row4[c * 8 + k];
                    p += v.x * qv[c].x + v.y * qv[c].y + v.z * qv[c].z + v.w * qv[c].w;
                }
                p += __shfl_xor_sync(0xffffffffu, p, 4);
                p += __shfl_xor_sync(0xffffffffu, p, 2);
                p += __shfl_xor_sync(0xffffffffu, p, 1);
                if (l >= Lb) e = __expf(p);
            }
            if (k == 0) { s_logits[l] = e; wsum += e; }
        }
        // combine the 4 k==0 lanes (0,8,16,24)
        wsum += __shfl_xor_sync(0xffffffffu, wsum, 16);
        wsum += __shfl_xor_sync(0xffffffffu, wsum, 8);
        if (lane == 0) s_red[warp] = wsum;
        __syncthreads();

        // every thread privately computes 1/total (16 broadcast LDS, no barrier)
        float tot = 0.f;
#pragma unroll
        for (int w = 0; w < 16; ++w) tot += s_red[w];
        const float inv = __frcp_rn(tot);

        // ---- pass 2: out[h] = inv * sum_l e_l * hist[l][h] (SMEM only) ----
        float4 a4 = {0.f, 0.f, 0.f, 0.f};
        for (int l = warp; l < LL; l += 16) {
            const float sc = s_logits[l];
            float4 v = s4[l * 32 + lane];
            a4.x = fmaf(sc, v.x, a4.x);
            a4.y = fmaf(sc, v.y, a4.y);
            a4.z = fmaf(sc, v.z, a4.z);
            a4.w = fmaf(sc, v.w, a4.w);
        }
        a4.x *= inv; a4.y *= inv; a4.z *= inv; a4.w *= inv;
        s_part[warp * 32 + lane] = a4;
        __syncthreads();   // all buf[cur] reads done after this

        if (warp == 0) {
            float4 rr = s_part[lane];
#pragma unroll
            for (int g = 1; g < 16; ++g) {
                float4 p = s_part[g * 32 + lane];
                rr.x += p.x; rr.y += p.y; rr.z += p.z; rr.w += p.w;
            }
            ((float4*)(out + (size_t)b * HH))[lane] = rr;
        }
    }
}

// ---------------------------------------------------------------------------
extern "C" void kernel_launch(void* const* d_in, const int* in_sizes, int n_in,
                              void* d_out, int out_size) {
    // Bind inputs BY ELEMENT COUNT (all distinct) — immune to ordering.
    const float* query = nullptr;   // 1048576
    const float* hist  = nullptr;   // 209715200
    const void*  hlen  = nullptr;   // 8192
    const float* W     = nullptr;   // 16384
    for (int i = 0; i < n_in; ++i) {
        switch (in_sizes[i]) {
            case BB * QQ:      query = (const float*)d_in[i]; break;
            case BB * LL * HH: hist  = (const float*)d_in[i]; break;
            case BB:           hlen  = d_in[i];               break;
            case QQ * HH:      W     = (const float*)d_in[i]; break;
            default: break;
        }
    }
    float* out = (float*)d_out;

    const int smem1 = (QQ * HH + 64 * 132) * (int)sizeof(float);   // 99328
    const int smem2 = 53520 * 4 + 64;                               // 214144

    cudaFuncSetAttribute(qw_gemm_kernel,
                         cudaFuncAttributeMaxDynamicSharedMemorySize, smem1);
    cudaFuncSetAttribute(attn_pool_kernel,
                         cudaFuncAttributeMaxDynamicSharedMemorySize, smem2);

    qw_gemm_kernel<<<BB / 64, 256, smem1>>>(query, W, (const int*)hlen);
    attn_pool_kernel<<<GRID, NTHREADS, smem2>>>(hist, hlen, out);
}